// round 4
// baseline (speedup 1.0000x reference)
#include <cuda_runtime.h>
#include <math.h>
#include <stdint.h>

#define B_    16
#define T_    1000
#define INDIM 257
#define FEAT  771
#define H_    512
#define KN    9
#define KS    6
#define M_    (B_*T_)        /* 16000 rows, time-major: row = t*B + b */
#define H3    (3*H_)         /* 1536 */
#define A2K   (H_*KN)        /* 4608 */
#define XT_LD 784            /* padded lda for FEAT=771 (16B-aligned rows) */
#define PLANE ((size_t)M_*H_)

// ---------------- scratch (device globals; no allocation allowed) ----------
__device__ float g_xT[(size_t)M_*XT_LD];   // inputs transposed to (t,b) rows
__device__ float g_h0[(size_t)M_*H_];      // tanh(input GEMM)
__device__ float g_U [(size_t)M_*H3];      // SRU pre-activations (reused L0/L1)
__device__ float g_h1[(size_t)M_*H_];
__device__ float g_h2[(size_t)M_*H_];
__device__ float g_A2[(size_t)M_*A2K];     // pooled, feature = h*KN + kn

// ---------------- packed f32x2 helpers -------------------------------------
__device__ __forceinline__ unsigned long long ffma2(unsigned long long a,
                                                    unsigned long long b,
                                                    unsigned long long c) {
    unsigned long long d;
    asm("fma.rn.f32x2 %0, %1, %2, %3;" : "=l"(d) : "l"(a), "l"(b), "l"(c));
    return d;
}
__device__ __forceinline__ void unpk(unsigned long long v, float &lo, float &hi) {
    asm("mov.b64 {%0, %1}, %2;" : "=f"(lo), "=f"(hi) : "l"(v));
}

// ---------------- transpose (b,t,f) -> (t,b,f) -----------------------------
__global__ void transpose_kernel(const float* __restrict__ in, float* __restrict__ xT) {
    int row = blockIdx.x;                  // t*B + b
    int t = row >> 4, b = row & 15;
    const float* src = in + ((size_t)b*T_ + t)*FEAT;
    float* dst = xT + (size_t)row*XT_LD;
    for (int f = threadIdx.x; f < FEAT; f += blockDim.x) dst[f] = src[f];
}

// ---------------- SGEMM, 128x64x16 tile, FFMA2 math, fused epilogues -------
// EPI 0: C = acc                      (SRU U)
// EPI 1: C = tanh(acc + bias[n])      (input layer)
// EPI 2: out = sigmoid(acc+bias[n]) * inputs[...,257+n], write center slice
template<int EPI>
__global__ __launch_bounds__(256, 2)
void sgemm_kernel(const float* __restrict__ A, int lda,
                  const float* __restrict__ Bm, int ldb,
                  float* __restrict__ C, int ldc,
                  int N, int K,
                  const float* __restrict__ bias,
                  const float* __restrict__ inp,
                  float* __restrict__ outp)
{
    const int BM = 128, BN = 64, BK = 16;
    __shared__ float As[BK][BM];
    __shared__ float Bs2[BK][BN*2];     // duplicated pairs: Bs2[k][2n]=Bs2[k][2n+1]=B[k][n]

    int tid   = threadIdx.x;
    int mBase = blockIdx.y * BM;
    int nBase = blockIdx.x * BN;
    int tx = tid & 15;          // n dir (16 * TN=4 = 64)
    int ty = tid >> 4;          // m dir (16 * TM=8 = 128)

    int aRow = tid >> 2;        // 0..63
    int aCol = (tid & 3) * 4;   // 0,4,8,12
    int bRow = tid >> 4;        // 0..15
    int bCol = (tid & 15) * 4;  // 0..60

    unsigned long long acc2[4][4];      // [m-pair][n], each packs (m_even, m_odd)
    #pragma unroll
    for (int i = 0; i < 4; i++)
        #pragma unroll
        for (int j = 0; j < 4; j++) acc2[i][j] = 0ull;

    for (int k0 = 0; k0 < K; k0 += BK) {
        bool full = (k0 + BK <= K);
        // --- load A tile (128x16), store transposed As[k][m]
        #pragma unroll
        for (int r = 0; r < 2; r++) {
            size_t off = (size_t)(mBase + aRow + r*64)*lda + k0 + aCol;
            float v0, v1, v2, v3;
            if (full) {
                float4 v = *reinterpret_cast<const float4*>(A + off);
                v0 = v.x; v1 = v.y; v2 = v.z; v3 = v.w;
            } else {
                v0 = (k0+aCol+0 < K) ? A[off+0] : 0.f;
                v1 = (k0+aCol+1 < K) ? A[off+1] : 0.f;
                v2 = (k0+aCol+2 < K) ? A[off+2] : 0.f;
                v3 = (k0+aCol+3 < K) ? A[off+3] : 0.f;
            }
            As[aCol+0][aRow + r*64] = v0;
            As[aCol+1][aRow + r*64] = v1;
            As[aCol+2][aRow + r*64] = v2;
            As[aCol+3][aRow + r*64] = v3;
        }
        // --- load B tile (16x64) scalar (handles misaligned ldb), write duplicated
        {
            int k = k0 + bRow;
            float v0 = 0.f, v1 = 0.f, v2 = 0.f, v3 = 0.f;
            if (k < K) {
                size_t off = (size_t)k*ldb + nBase + bCol;
                int n = nBase + bCol;
                if (n + 3 < N) {
                    v0 = Bm[off+0]; v1 = Bm[off+1]; v2 = Bm[off+2]; v3 = Bm[off+3];
                } else {
                    if (n+0 < N) v0 = Bm[off+0];
                    if (n+1 < N) v1 = Bm[off+1];
                    if (n+2 < N) v2 = Bm[off+2];
                    if (n+3 < N) v3 = Bm[off+3];
                }
            }
            float4 lo; lo.x = v0; lo.y = v0; lo.z = v1; lo.w = v1;
            float4 hi; hi.x = v2; hi.y = v2; hi.z = v3; hi.w = v3;
            *reinterpret_cast<float4*>(&Bs2[bRow][bCol*2])     = lo;
            *reinterpret_cast<float4*>(&Bs2[bRow][bCol*2 + 4]) = hi;
        }
        __syncthreads();

        #pragma unroll
        for (int kk = 0; kk < BK; kk++) {
            ulonglong2 a01 = *reinterpret_cast<const ulonglong2*>(&As[kk][ty*8]);
            ulonglong2 a23 = *reinterpret_cast<const ulonglong2*>(&As[kk][ty*8+4]);
            ulonglong2 b01 = *reinterpret_cast<const ulonglong2*>(&Bs2[kk][tx*8]);
            ulonglong2 b23 = *reinterpret_cast<const ulonglong2*>(&Bs2[kk][tx*8+4]);
            unsigned long long ap[4] = {a01.x, a01.y, a23.x, a23.y};
            unsigned long long bp[4] = {b01.x, b01.y, b23.x, b23.y};
            #pragma unroll
            for (int i = 0; i < 4; i++)
                #pragma unroll
                for (int j = 0; j < 4; j++)
                    acc2[i][j] = ffma2(ap[i], bp[j], acc2[i][j]);
        }
        __syncthreads();
    }

    if (EPI == 0) {
        #pragma unroll
        for (int i2 = 0; i2 < 4; i2++) {
            float lo[4], hi[4];
            #pragma unroll
            for (int j = 0; j < 4; j++) unpk(acc2[i2][j], lo[j], hi[j]);
            int m0 = mBase + ty*8 + 2*i2;
            float4 vl; vl.x = lo[0]; vl.y = lo[1]; vl.z = lo[2]; vl.w = lo[3];
            float4 vh; vh.x = hi[0]; vh.y = hi[1]; vh.z = hi[2]; vh.w = hi[3];
            *reinterpret_cast<float4*>(&C[(size_t)m0*ldc + nBase + tx*4])     = vl;
            *reinterpret_cast<float4*>(&C[(size_t)(m0+1)*ldc + nBase + tx*4]) = vh;
        }
    } else {
        float acc[8][4];
        #pragma unroll
        for (int i2 = 0; i2 < 4; i2++)
            #pragma unroll
            for (int j = 0; j < 4; j++)
                unpk(acc2[i2][j], acc[2*i2][j], acc[2*i2+1][j]);
        #pragma unroll
        for (int i = 0; i < 8; i++) {
            int m = mBase + ty*8 + i;
            #pragma unroll
            for (int j = 0; j < 4; j++) {
                int n = nBase + tx*4 + j;
                if (n >= N) continue;
                float v = acc[i][j] + bias[n];
                if (EPI == 1) {
                    C[(size_t)m*ldc + n] = tanhf(v);
                } else {
                    float s = 1.f / (1.f + __expf(-v));
                    int b = m & 15, t = m >> 4;
                    size_t row = (size_t)b*T_ + t;
                    outp[row*INDIM + n] = s * inp[row*FEAT + INDIM + n];
                }
            }
        }
    }
}

// ---------------- SRU scan: one thread per (b,h), pipelined over t ---------
#define SUN 8
__global__ void scan_kernel(const float* __restrict__ U,
                            const float* __restrict__ X,
                            const float* __restrict__ v,
                            const float* __restrict__ bb,
                            float* __restrict__ Hout)
{
    int idx = blockIdx.x * blockDim.x + threadIdx.x;   // 0..B*H-1
    int b = idx >> 9, h = idx & (H_-1);
    float vf = v[h], vr = v[H_ + h];
    float bf = bb[h], br = bb[H_ + h];
    const float* Ub = U + (size_t)b*H3 + h;
    const float* Xb = X + (size_t)b*H_ + h;
    float*       Hb = Hout + (size_t)b*H_ + h;

    float cxt[SUN], cfp[SUN], crp[SUN], cxn[SUN];
    #pragma unroll
    for (int u = 0; u < SUN; u++) {
        size_t o3 = (size_t)u * (B_*H3);
        size_t o1 = (size_t)u * (B_*H_);
        cxt[u] = Ub[o3]; cfp[u] = Ub[o3 + H_]; crp[u] = Ub[o3 + 2*H_];
        cxn[u] = Xb[o1];
    }
    float c = 0.f;
    for (int t0 = 0; t0 < T_; t0 += SUN) {
        float nxt[SUN], nfp[SUN], nrp[SUN], nxn[SUN];
        bool more = (t0 + SUN < T_);
        #pragma unroll
        for (int u = 0; u < SUN; u++) {
            int t = t0 + SUN + u;
            size_t o3 = (size_t)t * (B_*H3);
            size_t o1 = (size_t)t * (B_*H_);
            if (more) {
                nxt[u] = Ub[o3]; nfp[u] = Ub[o3 + H_]; nrp[u] = Ub[o3 + 2*H_];
                nxn[u] = Xb[o1];
            } else { nxt[u] = nfp[u] = nrp[u] = nxn[u] = 0.f; }
        }
        #pragma unroll
        for (int u = 0; u < SUN; u++) {
            float f = 1.f / (1.f + __expf(-(fmaf(vf, c, cfp[u]) + bf)));
            float cn = fmaf(f, c - cxt[u], cxt[u]);
            float r = 1.f / (1.f + __expf(-(fmaf(vr, c, crp[u]) + br)));
            Hb[(size_t)(t0+u) * (B_*H_)] = fmaf(r, cn - cxn[u], cxn[u]);
            c = cn;
        }
        #pragma unroll
        for (int u = 0; u < SUN; u++) {
            cxt[u] = nxt[u]; cfp[u] = nfp[u]; crp[u] = nrp[u]; cxn[u] = nxn[u];
        }
    }
}

// ---------------- fused conv6x6 + maxpool3x3 + tanh ------------------------
// Block computes 8x32 pooled outputs. Needs raw conv on 10x34 (1-halo),
// which needs the 15x39 input tile (rows t0-4..t0+10, cols h0-4..h0+34).
// tanh monotonic => pool raw conv, then tanh(max + bias).
// Invalid conv positions (outside TxH) = -inf.
__global__ __launch_bounds__(256)
void convpool_kernel(const float* __restrict__ w, const float* __restrict__ cb,
                     const float* __restrict__ in, float* __restrict__ A2)
{
    __shared__ float ws[KN][KS][KS];
    __shared__ float bs[KN];
    __shared__ float xin[15][40];
    __shared__ float cv[KN][10][36];
    __shared__ float po[8][32*KN];

    int b  = blockIdx.z;
    int t0 = blockIdx.y * 8;
    int h0 = blockIdx.x * 32;
    int tid = threadIdx.x;

    for (int i = tid; i < KN*KS*KS; i += 256) (&ws[0][0][0])[i] = w[i];
    if (tid < KN) bs[tid] = cb[tid];
    for (int i = tid; i < 15*39; i += 256) {
        int r = i / 39, cc = i % 39;
        int t = t0 - 4 + r, h = h0 - 4 + cc;
        float val = 0.f;
        if (t >= 0 && t < T_ && h >= 0 && h < H_)
            val = in[((size_t)t*B_ + b)*H_ + h];
        xin[r][cc] = val;
    }
    __syncthreads();

    // raw conv on 10x34 halo region
    for (int p = tid; p < 10*34; p += 256) {
        int r = p / 34, cc = p % 34;          // conv coords: t=t0-1+r, h=h0-1+cc
        int tt = t0 - 1 + r, hh = h0 - 1 + cc;
        float acc[KN];
        #pragma unroll
        for (int kn = 0; kn < KN; kn++) acc[kn] = 0.f;
        #pragma unroll
        for (int i = 0; i < KS; i++)
            #pragma unroll
            for (int j = 0; j < KS; j++) {
                float x = xin[r + i][cc + j];
                #pragma unroll
                for (int kn = 0; kn < KN; kn++)
                    acc[kn] = fmaf(ws[kn][i][j], x, acc[kn]);
            }
        bool valid = (tt >= 0 && tt < T_ && hh >= 0 && hh < H_);
        #pragma unroll
        for (int kn = 0; kn < KN; kn++)
            cv[kn][r][cc] = valid ? acc[kn] : -3.0e38f;
    }
    __syncthreads();

    // pool 3x3 + tanh; one output per thread
    {
        int ht = tid & 31, tt = tid >> 5;
        #pragma unroll
        for (int kn = 0; kn < KN; kn++) {
            float m = -3.0e38f;
            #pragma unroll
            for (int dt = 0; dt < 3; dt++)
                #pragma unroll
                for (int dh = 0; dh < 3; dh++)
                    m = fmaxf(m, cv[kn][tt + dt][ht + dh]);
            po[tt][ht*KN + kn] = tanhf(m + bs[kn]);
        }
    }
    __syncthreads();

    // coalesced write: 8 rows x 288 contiguous features
    for (int i = tid; i < 8*32*KN; i += 256) {
        int row = i / (32*KN), f = i % (32*KN);
        A2[((size_t)(t0 + row)*B_ + b)*A2K + (size_t)h0*KN + f] = po[row][f];
    }
}

// ---------------- driver ---------------------------------------------------
extern "C" void kernel_launch(void* const* d_in, const int* in_sizes, int n_in,
                              void* d_out, int out_size)
{
    const float* inputs = (const float*)d_in[0];
    const float* W_in   = (const float*)d_in[1];
    const float* b_in   = (const float*)d_in[2];
    const float* W_rnn  = (const float*)d_in[3];
    const float* v_rnn  = (const float*)d_in[4];
    const float* b_rnn  = (const float*)d_in[5];
    const float* conv_k = (const float*)d_in[6];
    const float* conv_b = (const float*)d_in[7];
    const float* W_out  = (const float*)d_in[8];
    const float* b_out  = (const float*)d_in[9];
    float* out = (float*)d_out;

    float *xT, *h0, *U, *h1, *h2, *A2;
    cudaGetSymbolAddress((void**)&xT, g_xT);
    cudaGetSymbolAddress((void**)&h0, g_h0);
    cudaGetSymbolAddress((void**)&U,  g_U);
    cudaGetSymbolAddress((void**)&h1, g_h1);
    cudaGetSymbolAddress((void**)&h2, g_h2);
    cudaGetSymbolAddress((void**)&A2, g_A2);

    // 1. transpose inputs to time-major (padded rows for alignment)
    transpose_kernel<<<M_, 256>>>(inputs, xT);

    // 2. input layer: tanh(xT @ W_in + b_in) -> h0   (M=16000, N=512, K=771)
    sgemm_kernel<1><<<dim3(512/64, M_/128), 256>>>(
        xT, XT_LD, W_in, H_, h0, H_, H_, FEAT, b_in, nullptr, nullptr);

    // 3. SRU layer 0
    sgemm_kernel<0><<<dim3(H3/64, M_/128), 256>>>(
        h0, H_, W_rnn, H3, U, H3, H3, H_, nullptr, nullptr, nullptr);
    scan_kernel<<<(B_*H_)/128, 128>>>(U, h0, v_rnn, b_rnn, h1);

    // 4. SRU layer 1
    sgemm_kernel<0><<<dim3(H3/64, M_/128), 256>>>(
        h1, H_, W_rnn + (size_t)H_*H3, H3, U, H3, H3, H_, nullptr, nullptr, nullptr);
    scan_kernel<<<(B_*H_)/128, 128>>>(U, h1, v_rnn + 2*H_, b_rnn + 2*H_, h2);

    // 5+6. fused conv + pool + tanh -> A2 (m, h*KN+kn)
    convpool_kernel<<<dim3(H_/32, T_/8, B_), 256>>>(conv_k, conv_b, h2, A2);

    // 7. output GEMM on the needed 257 columns only, fused sigmoid*input
    sgemm_kernel<2><<<dim3((INDIM + 63)/64, M_/128), 256>>>(
        A2, A2K, W_out + INDIM, FEAT, nullptr, 0, INDIM, A2K,
        b_out + INDIM, inputs, out);
}